// round 15
// baseline (speedup 1.0000x reference)
#include <cuda_runtime.h>
#include <cstdint>

// Problem constants
#define NPTS 100000
#define CIN  16
#define FOUT 16
#define BW   8
#define NDIM 3
#define NSEG 8192

// Pre-conv (fp16 mma.sync m16n8k16) tiling — fully persistent (1 wave)
#define PN    32                  // points per tile -> 256 output rows
#define T1    256                 // 8 warps; warp covers 32 rows (2 m16 tiles)
#define NTILE (NPTS / PN)         // 3125
#define NBX   148                 // grid.x == SM count -> ~21 tiles/CTA
#define XS_WORDS (34 * 10 * 8)    // 2720
#define WB_WORDS (144 * 8)        // 1152

__device__ __forceinline__ uint32_t pack_f16x2(float lo, float hi) {
    uint32_t r;
    asm("cvt.rn.f16x2.f32 %0, %1, %2;" : "=r"(r) : "f"(hi), "f"(lo));
    return r;
}

#define MMA_F16(acc, a0, a1, a2, a3, b0, b1)                                   \
    asm("mma.sync.aligned.m16n8k16.row.col.f32.f16.f16.f32 "                   \
        "{%0,%1,%2,%3},{%4,%5,%6,%7},{%8,%9},{%0,%1,%2,%3};"                   \
        : "+f"(acc[0]), "+f"(acc[1]), "+f"(acc[2]), "+f"(acc[3])               \
        : "r"(a0), "r"(a1), "r"(a2), "r"(a3), "r"(b0), "r"(b1))

// Device scratch (static allocation — no cudaMalloc allowed)
__device__ float    g_seg[NDIM * NSEG * BW * FOUT];   // segment sums
__device__ float    g_z  [NDIM * NSEG * BW * FOUT];   // post-conv output
__device__ uint32_t g_wb [NDIM * WB_WORDS];           // permuted fp16 weights
__device__ float    g_bs [NDIM * FOUT];               // bias

// ---------------------------------------------------------------------------
// Kernel 0: zero the segment-sum scratch
// ---------------------------------------------------------------------------
__global__ void zero_seg_kernel() {
    const int total = NDIM * NSEG * BW * FOUT / 4;
    float4* p = reinterpret_cast<float4*>(g_seg);
    const float4 z = make_float4(0.f, 0.f, 0.f, 0.f);
    for (int i = blockIdx.x * blockDim.x + threadIdx.x; i < total;
         i += gridDim.x * blockDim.x)
        p[i] = z;
}

// ---------------------------------------------------------------------------
// Kernel 0b: permute + convert pre-conv weights to fp16 once.
// Storage row s = nt*8+n holds filter 4*(n>>1)+2*nt+(n&1); word j holds
// channel pair (c, c+1), c = j odd ? j+7 : j.
// ---------------------------------------------------------------------------
__global__ void weight_setup_kernel(const float* __restrict__ pre_w,
                                    const float* __restrict__ pre_b) {
    for (int gi = blockIdx.x * blockDim.x + threadIdx.x; gi < NDIM * WB_WORDS;
         gi += gridDim.x * blockDim.x) {
        const int d   = gi / WB_WORDS;
        const int i   = gi - d * WB_WORDS;
        const int tap = i >> 7;
        const int rem = i & 127;
        const int s   = rem >> 3;
        const int j   = rem & 7;
        const int nt  = s >> 3;
        const int n   = s & 7;
        const int fpm = 4 * (n >> 1) + 2 * nt + (n & 1);
        const int c   = (j & 1) ? (j + 7) : j;
        const int base = d * 2304 + tap * 256;
        g_wb[gi] = pack_f16x2(pre_w[base + c * 16 + fpm],
                              pre_w[base + (c + 1) * 16 + fpm]);
    }
    const int t = blockIdx.x * blockDim.x + threadIdx.x;
    if (t < NDIM * FOUT) g_bs[t] = pre_b[t];
}

// ---------------------------------------------------------------------------
// Kernel 1: gather X[inv] -> fp16 mma 3x3 conv -> relu -> atomic seg-sum
// grid (148, 3) — ONE resident wave, each CTA strides tiles by 148.
// Setup (weights/bias/pad-zero) paid once per CTA. Gather zero-fills
// out-of-range halo rows; TWO __syncthreads() per tile.
// RACE FIX vs R14: ALL bias reads from bs[] happen AFTER the setup sync.
// ---------------------------------------------------------------------------
__global__ void __launch_bounds__(T1)
pre_conv_mma_kernel(const float* __restrict__ X, const int* __restrict__ inv,
                    const int* __restrict__ index)
{
    __shared__ uint32_t xs[XS_WORDS];
    __shared__ uint32_t wb[WB_WORDS];
    __shared__ float    bs[16];

    const int tid  = threadIdx.x;
    const int wid  = tid >> 5;
    const int lane = tid & 31;
    const int q    = lane & 3;    // fragment k-quad / D col group
    const int lr   = lane >> 2;   // fragment row / B n index (0..7)
    const int d    = blockIdx.y;

    // One-time: coalesced weight/bias load + pad-slot zeroing
    {
        const uint4* src = reinterpret_cast<const uint4*>(g_wb + d * WB_WORDS);
        uint4* dst = reinterpret_cast<uint4*>(wb);
        for (int i = tid; i < WB_WORDS / 4; i += T1) dst[i] = src[i];
        if (tid < FOUT) bs[tid] = g_bs[d * FOUT + tid];
        // w-pad slots (wslot 0 and 9): never written by gather
        for (int i = tid; i < 34 * 16; i += T1) {
            const int pt = i >> 4, rem = i & 15;
            const int wslot = (rem < 8) ? 0 : 9;
            xs[(pt * 10 + wslot) * 8 + (rem & 7)] = 0u;
        }
    }

    // Register-only invariants (no shared reads here)
    int base_lo[2], base_hi[2];
#pragma unroll
    for (int mt = 0; mt < 2; ++mt) {
        const int ptl = wid * 4 + mt * 2;
        base_lo[mt] = (ptl * 10 + lr) * 8 + 2 * q;
        base_hi[mt] = base_lo[mt] + 80;
    }

    __syncthreads();   // publishes wb, bs, xs pad slots

    // Bias reads strictly AFTER the sync (R14's race was here)
    const float b0v = bs[4 * q + 0], b1v = bs[4 * q + 1];
    const float b2v = bs[4 * q + 2], b3v = bs[4 * q + 3];

#pragma unroll 1
    for (int tile = blockIdx.x; tile < NTILE; tile += NBX) {
        const int bstart = tile * PN;

        // Quad-cooperative gather, zero-filling out-of-range halo rows.
        // 272 rows x 4 quarters = 1088 lane tasks.
        for (int i = tid; i < 34 * 8 * 4; i += T1) {
            const int r  = i >> 2;          // row 0..271
            const int tq = i & 3;           // 16B quarter
            const int pt = r >> 3;
            const int w  = r & 7;
            const int gp = bstart - 1 + pt;
            float4 v = make_float4(0.f, 0.f, 0.f, 0.f);
            if ((unsigned)gp < NPTS) {
                const int idx = inv[(d * NPTS + gp) * BW + w];
                v = reinterpret_cast<const float4*>(X)[idx * 4 + tq];
            }
            const int woff = (pt * 10 + w + 1) * 8 + 4 * (tq & 1) + (tq >> 1);
            xs[woff]     = pack_f16x2(v.x, v.y);
            xs[woff + 2] = pack_f16x2(v.z, v.w);
        }

        // Prefetch epilogue segment ids (drain under the MMA stream)
        int seg_l[2], seg_h[2];
#pragma unroll
        for (int mt = 0; mt < 2; ++mt) {
            const int ptl = wid * 4 + mt * 2;
            seg_l[mt] = index[d * NPTS + bstart + ptl];
            seg_h[mt] = index[d * NPTS + bstart + ptl + 1];
        }
        __syncthreads();   // gather writes visible

        float acc[2][2][4];
#pragma unroll
        for (int mt = 0; mt < 2; ++mt)
#pragma unroll
            for (int nt = 0; nt < 2; ++nt)
#pragma unroll
                for (int i = 0; i < 4; ++i) acc[mt][nt][i] = 0.f;

#pragma unroll
        for (int a = 0; a < 3; ++a) {
#pragma unroll
            for (int b = 0; b < 3; ++b) {
                const int tap  = a * 3 + b;
                const int toff = (a * 10 + b) * 8;
                const uint2 bf0 = *reinterpret_cast<const uint2*>(
                    wb + (tap * 16 + lr) * 8 + 2 * q);
                const uint2 bf1 = *reinterpret_cast<const uint2*>(
                    wb + (tap * 16 + 8 + lr) * 8 + 2 * q);
#pragma unroll
                for (int mt = 0; mt < 2; ++mt) {
                    const uint2 alo = *reinterpret_cast<const uint2*>(
                        xs + base_lo[mt] + toff);
                    const uint2 ahi = *reinterpret_cast<const uint2*>(
                        xs + base_hi[mt] + toff);
                    MMA_F16(acc[mt][0], alo.x, ahi.x, alo.y, ahi.y, bf0.x, bf0.y);
                    MMA_F16(acc[mt][1], alo.x, ahi.x, alo.y, ahi.y, bf1.x, bf1.y);
                }
            }
        }
        __syncthreads();   // xs reads done; next tile's gather may overwrite

        // Epilogue: bias + relu + ONE red.v4 per (mt, half); filters [4q,4q+4)
#pragma unroll
        for (int mt = 0; mt < 2; ++mt) {
            float* bl = g_seg + ((d * NSEG + seg_l[mt]) * BW + lr) * FOUT + 4 * q;
            float* bh = g_seg + ((d * NSEG + seg_h[mt]) * BW + lr) * FOUT + 4 * q;
            {
                const float v0 = fmaxf(acc[mt][0][0] + b0v, 0.f);
                const float v1 = fmaxf(acc[mt][0][1] + b1v, 0.f);
                const float v2 = fmaxf(acc[mt][1][0] + b2v, 0.f);
                const float v3 = fmaxf(acc[mt][1][1] + b3v, 0.f);
                asm volatile("red.global.add.v4.f32 [%0], {%1,%2,%3,%4};"
                             :: "l"(bl), "f"(v0), "f"(v1), "f"(v2), "f"(v3)
                             : "memory");
            }
            {
                const float v0 = fmaxf(acc[mt][0][2] + b0v, 0.f);
                const float v1 = fmaxf(acc[mt][0][3] + b1v, 0.f);
                const float v2 = fmaxf(acc[mt][1][2] + b2v, 0.f);
                const float v3 = fmaxf(acc[mt][1][3] + b3v, 0.f);
                asm volatile("red.global.add.v4.f32 [%0], {%1,%2,%3,%4};"
                             :: "l"(bh), "f"(v0), "f"(v1), "f"(v2), "f"(v3)
                             : "memory");
            }
        }
    }
}

// ---------------------------------------------------------------------------
// Kernel 2: post conv (3,1) + relu on g_seg -> g_z.
// All 12 row-loads hoisted as independent predicated LDG.128 (MLP 12).
// ---------------------------------------------------------------------------
__global__ void __launch_bounds__(128)
post_conv_kernel(const float* __restrict__ post_w, const float* __restrict__ post_b)
{
    __shared__ float ws[768];
    __shared__ float bs[16];
    const int tid = threadIdx.x;
    const int d   = blockIdx.y;
    for (int i = tid; i < 768; i += 128) ws[i] = post_w[d * 768 + i];
    if (tid < FOUT) bs[tid] = post_b[d * FOUT + tid];
    __syncthreads();

    const int gt = blockIdx.x * 128 + tid;    // 0 .. NSEG*BW-1
    const int s  = gt >> 3;
    const int w  = gt & 7;

    // Hoisted loads: 12 independent predicated LDG.128
    float4 xv[12];
#pragma unroll
    for (int a = 0; a < 3; ++a) {
        const int ss = s + a - 1;
        const bool ok = (unsigned)ss < NSEG;
        const float4* src = reinterpret_cast<const float4*>(
            g_seg + ((d * NSEG + (ok ? ss : 0)) * BW + w) * FOUT);
#pragma unroll
        for (int cg = 0; cg < 4; ++cg) {
            float4 v = make_float4(0.f, 0.f, 0.f, 0.f);
            if (ok) v = src[cg];
            xv[a * 4 + cg] = v;
        }
    }

    float acc[16];
#pragma unroll
    for (int f = 0; f < 16; ++f) acc[f] = 0.f;

#pragma unroll
    for (int a = 0; a < 3; ++a) {
#pragma unroll
        for (int cg = 0; cg < 4; ++cg) {
            const float4 x4 = xv[a * 4 + cg];
            const float* wr = ws + (a * 16 + cg * 4) * 16;
#pragma unroll
            for (int f = 0; f < 16; ++f) acc[f] += x4.x * wr[f];
#pragma unroll
            for (int f = 0; f < 16; ++f) acc[f] += x4.y * wr[16 + f];
#pragma unroll
            for (int f = 0; f < 16; ++f) acc[f] += x4.z * wr[32 + f];
#pragma unroll
            for (int f = 0; f < 16; ++f) acc[f] += x4.w * wr[48 + f];
        }
    }

    float4* dst = reinterpret_cast<float4*>(g_z + ((d * NSEG + s) * BW + w) * FOUT);
#pragma unroll
    for (int fg = 0; fg < 4; ++fg) {
        float4 v;
        v.x = fmaxf(acc[fg * 4 + 0] + bs[fg * 4 + 0], 0.f);
        v.y = fmaxf(acc[fg * 4 + 1] + bs[fg * 4 + 1], 0.f);
        v.z = fmaxf(acc[fg * 4 + 2] + bs[fg * 4 + 2], 0.f);
        v.w = fmaxf(acc[fg * 4 + 3] + bs[fg * 4 + 3], 0.f);
        dst[fg] = v;
    }
}

// ---------------------------------------------------------------------------
// Kernel 3: Y[n,w,:] = sum_d g_z[d, index[d,n], w, :]
// Each thread: two n's -> 6 independent L2 loads in flight.
// ---------------------------------------------------------------------------
__global__ void __launch_bounds__(256)
gather_out_kernel(const int* __restrict__ index, float* __restrict__ out)
{
    const int gt = blockIdx.x * 256 + threadIdx.x;
    if (gt >= NPTS * BW * 2) return;
    const int n   = gt >> 5;
    const int rem = gt & 31;
    const int n2  = n + NPTS / 2;

    const int s0 = index[n],            t0 = index[n2];
    const int s1 = index[NPTS + n],     t1 = index[NPTS + n2];
    const int s2 = index[2 * NPTS + n], t2 = index[2 * NPTS + n2];

    const float4 a0 = reinterpret_cast<const float4*>(
        g_z + (size_t)s0 * (BW * FOUT))[rem];
    const float4 a1 = reinterpret_cast<const float4*>(
        g_z + (size_t)(NSEG + s1) * (BW * FOUT))[rem];
    const float4 a2 = reinterpret_cast<const float4*>(
        g_z + (size_t)(2 * NSEG + s2) * (BW * FOUT))[rem];
    const float4 c0 = reinterpret_cast<const float4*>(
        g_z + (size_t)t0 * (BW * FOUT))[rem];
    const float4 c1 = reinterpret_cast<const float4*>(
        g_z + (size_t)(NSEG + t1) * (BW * FOUT))[rem];
    const float4 c2 = reinterpret_cast<const float4*>(
        g_z + (size_t)(2 * NSEG + t2) * (BW * FOUT))[rem];

    float4 r;
    r.x = a0.x + a1.x + a2.x; r.y = a0.y + a1.y + a2.y;
    r.z = a0.z + a1.z + a2.z; r.w = a0.w + a1.w + a2.w;
    reinterpret_cast<float4*>(out)[n * 32 + rem] = r;

    float4 r2;
    r2.x = c0.x + c1.x + c2.x; r2.y = c0.y + c1.y + c2.y;
    r2.z = c0.z + c1.z + c2.z; r2.w = c0.w + c1.w + c2.w;
    reinterpret_cast<float4*>(out)[n2 * 32 + rem] = r2;
}

// ---------------------------------------------------------------------------
extern "C" void kernel_launch(void* const* d_in, const int* in_sizes, int n_in,
                              void* d_out, int out_size)
{
    const float* X      = (const float*)d_in[0];
    const int*   inv    = (const int*)  d_in[1];
    const int*   index  = (const int*)  d_in[2];
    const float* pre_w  = (const float*)d_in[3];
    const float* pre_b  = (const float*)d_in[4];
    const float* post_w = (const float*)d_in[5];
    const float* post_b = (const float*)d_in[6];
    float*       out    = (float*)      d_out;

    zero_seg_kernel<<<2048, 256>>>();
    weight_setup_kernel<<<16, 256>>>(pre_w, pre_b);

    dim3 g1(NBX, NDIM);
    pre_conv_mma_kernel<<<g1, T1>>>(X, inv, index);

    dim3 g2(NSEG * BW / 128, NDIM);
    post_conv_kernel<<<g2, 128>>>(post_w, post_b);

    gather_out_kernel<<<(NPTS * BW * 2 + 255) / 256, 256>>>(index, out);
}

// round 16
// speedup vs baseline: 1.2151x; 1.2151x over previous
#include <cuda_runtime.h>
#include <cstdint>

// Problem constants
#define NPTS 100000
#define CIN  16
#define FOUT 16
#define BW   8
#define NDIM 3
#define NSEG 8192

// Pre-conv (fp16 mma.sync m16n8k16) tiling — R13 proven configuration
#define PN    32                  // points per tile -> 256 output rows
#define T1    256                 // 8 warps; warp covers 32 rows (2 m16 tiles)
#define NTILE (NPTS / PN)         // 3125
#define TPC   5                   // tiles per CTA
#define NBX   (NTILE / TPC)       // 625
#define XS_WORDS (34 * 10 * 8)    // 2720
#define WB_WORDS (144 * 8)        // 1152  (pre weights)
#define WB2_WORDS (48 * 8)        // 384   (post weights: 3 taps x 16 rows x 8)

__device__ __forceinline__ uint32_t pack_f16x2(float lo, float hi) {
    uint32_t r;
    asm("cvt.rn.f16x2.f32 %0, %1, %2;" : "=r"(r) : "f"(hi), "f"(lo));
    return r;
}

#define MMA_F16(acc, a0, a1, a2, a3, b0, b1)                                   \
    asm("mma.sync.aligned.m16n8k16.row.col.f32.f16.f16.f32 "                   \
        "{%0,%1,%2,%3},{%4,%5,%6,%7},{%8,%9},{%0,%1,%2,%3};"                   \
        : "+f"(acc[0]), "+f"(acc[1]), "+f"(acc[2]), "+f"(acc[3])               \
        : "r"(a0), "r"(a1), "r"(a2), "r"(a3), "r"(b0), "r"(b1))

// Device scratch (static allocation — no cudaMalloc allowed)
__device__ float    g_seg[NDIM * NSEG * BW * FOUT];   // segment sums
__device__ float    g_z  [NDIM * NSEG * BW * FOUT];   // post-conv output
__device__ uint32_t g_wb [NDIM * WB_WORDS];           // permuted fp16 pre weights
__device__ uint32_t g_wb2[NDIM * WB2_WORDS];          // permuted fp16 post weights
__device__ float    g_bs [NDIM * FOUT];               // pre bias
__device__ float    g_bs2[NDIM * FOUT];               // post bias

// ---------------------------------------------------------------------------
// Kernel 0: zero g_seg + build all permuted fp16 weights + biases (one launch)
// Weight storage row s = nt*8+n holds filter 4*(n>>1)+2*nt+(n&1); word j holds
// channel pair (c, c+1), c = j odd ? j+7 : j.
// ---------------------------------------------------------------------------
__global__ void setup_kernel(const float* __restrict__ pre_w,
                             const float* __restrict__ pre_b,
                             const float* __restrict__ post_w,
                             const float* __restrict__ post_b) {
    const int gt = blockIdx.x * blockDim.x + threadIdx.x;

    // Zero g_seg (grid-stride, float4)
    {
        const int total = NDIM * NSEG * BW * FOUT / 4;
        float4* p = reinterpret_cast<float4*>(g_seg);
        const float4 z = make_float4(0.f, 0.f, 0.f, 0.f);
        for (int i = gt; i < total; i += gridDim.x * blockDim.x) p[i] = z;
    }

    // Pre-conv weights: 3456 words
    if (gt < NDIM * WB_WORDS) {
        const int d   = gt / WB_WORDS;
        const int i   = gt - d * WB_WORDS;
        const int tap = i >> 7;
        const int rem = i & 127;
        const int s   = rem >> 3;
        const int j   = rem & 7;
        const int nt  = s >> 3;
        const int n   = s & 7;
        const int fpm = 4 * (n >> 1) + 2 * nt + (n & 1);
        const int c   = (j & 1) ? (j + 7) : j;
        const int base = d * 2304 + tap * 256;
        g_wb[gt] = pack_f16x2(pre_w[base + c * 16 + fpm],
                              pre_w[base + (c + 1) * 16 + fpm]);
    }
    // Post-conv weights: 1152 words. post_w layout [d][tap(3)][1][c][f].
    if (gt < NDIM * WB2_WORDS) {
        const int d   = gt / WB2_WORDS;
        const int i   = gt - d * WB2_WORDS;
        const int tap = i >> 7;             // 0..2
        const int rem = i & 127;
        const int s   = rem >> 3;
        const int j   = rem & 7;
        const int nt  = s >> 3;
        const int n   = s & 7;
        const int fpm = 4 * (n >> 1) + 2 * nt + (n & 1);
        const int c   = (j & 1) ? (j + 7) : j;
        const int base = d * 768 + tap * 256;
        g_wb2[gt] = pack_f16x2(post_w[base + c * 16 + fpm],
                               post_w[base + (c + 1) * 16 + fpm]);
    }
    if (gt < NDIM * FOUT) {
        g_bs [gt] = pre_b [gt];
        g_bs2[gt] = post_b[gt];
    }
}

// ---------------------------------------------------------------------------
// Kernel 1: gather X[inv] -> fp16 mma 3x3 conv -> relu -> atomic seg-sum
// (R13 proven-best structure: grid (625,3), TPC=5, per-tile edge-zeroing,
//  seg-id prefetch before MMA.)
// ---------------------------------------------------------------------------
__global__ void __launch_bounds__(T1)
pre_conv_mma_kernel(const float* __restrict__ X, const int* __restrict__ inv,
                    const int* __restrict__ index)
{
    __shared__ uint32_t xs[XS_WORDS];
    __shared__ uint32_t wb[WB_WORDS];
    __shared__ float    bs[16];

    const int tid  = threadIdx.x;
    const int wid  = tid >> 5;
    const int lane = tid & 31;
    const int q    = lane & 3;
    const int lr   = lane >> 2;
    const int d    = blockIdx.y;

    {
        const uint4* src = reinterpret_cast<const uint4*>(g_wb + d * WB_WORDS);
        uint4* dst = reinterpret_cast<uint4*>(wb);
        for (int i = tid; i < WB_WORDS / 4; i += T1) dst[i] = src[i];
        if (tid < FOUT) bs[tid] = g_bs[d * FOUT + tid];
        for (int i = tid; i < 34 * 16; i += T1) {
            const int pt = i >> 4, rem = i & 15;
            const int wslot = (rem < 8) ? 0 : 9;
            xs[(pt * 10 + wslot) * 8 + (rem & 7)] = 0u;
        }
    }

#pragma unroll 1
    for (int t = 0; t < TPC; ++t) {
        const int tile   = blockIdx.x + NBX * t;
        const int bstart = tile * PN;

        if (tile == 0) {
            for (int i = tid; i < 64; i += T1)
                xs[(0 * 10 + ((i >> 3) + 1)) * 8 + (i & 7)] = 0u;
        }
        if (tile == NTILE - 1) {
            for (int i = tid; i < 64; i += T1)
                xs[(33 * 10 + ((i >> 3) + 1)) * 8 + (i & 7)] = 0u;
        }
        __syncthreads();

        for (int i = tid; i < 34 * 8 * 4; i += T1) {
            const int r  = i >> 2;
            const int tq = i & 3;
            const int pt = r >> 3;
            const int w  = r & 7;
            const int gp = bstart - 1 + pt;
            if ((unsigned)gp >= NPTS) continue;
            const int idx = inv[(d * NPTS + gp) * BW + w];
            const float4 v = reinterpret_cast<const float4*>(X)[idx * 4 + tq];
            const int woff = (pt * 10 + w + 1) * 8 + 4 * (tq & 1) + (tq >> 1);
            xs[woff]     = pack_f16x2(v.x, v.y);
            xs[woff + 2] = pack_f16x2(v.z, v.w);
        }

        int seg_l[2], seg_h[2];
#pragma unroll
        for (int mt = 0; mt < 2; ++mt) {
            const int ptl = wid * 4 + mt * 2;
            seg_l[mt] = index[d * NPTS + bstart + ptl];
            seg_h[mt] = index[d * NPTS + bstart + ptl + 1];
        }
        __syncthreads();

        int base_lo[2], base_hi[2];
#pragma unroll
        for (int mt = 0; mt < 2; ++mt) {
            const int ptl = wid * 4 + mt * 2;
            base_lo[mt] = (ptl * 10 + lr) * 8 + 2 * q;
            base_hi[mt] = base_lo[mt] + 80;
        }

        float acc[2][2][4];
#pragma unroll
        for (int mt = 0; mt < 2; ++mt)
#pragma unroll
            for (int nt = 0; nt < 2; ++nt)
#pragma unroll
                for (int i = 0; i < 4; ++i) acc[mt][nt][i] = 0.f;

#pragma unroll
        for (int a = 0; a < 3; ++a) {
#pragma unroll
            for (int b = 0; b < 3; ++b) {
                const int tap  = a * 3 + b;
                const int toff = (a * 10 + b) * 8;
                const uint2 bf0 = *reinterpret_cast<const uint2*>(
                    wb + (tap * 16 + lr) * 8 + 2 * q);
                const uint2 bf1 = *reinterpret_cast<const uint2*>(
                    wb + (tap * 16 + 8 + lr) * 8 + 2 * q);
#pragma unroll
                for (int mt = 0; mt < 2; ++mt) {
                    const uint2 alo = *reinterpret_cast<const uint2*>(
                        xs + base_lo[mt] + toff);
                    const uint2 ahi = *reinterpret_cast<const uint2*>(
                        xs + base_hi[mt] + toff);
                    MMA_F16(acc[mt][0], alo.x, ahi.x, alo.y, ahi.y, bf0.x, bf0.y);
                    MMA_F16(acc[mt][1], alo.x, ahi.x, alo.y, ahi.y, bf1.x, bf1.y);
                }
            }
        }
        __syncthreads();

        const float b0v = bs[4 * q + 0], b1v = bs[4 * q + 1];
        const float b2v = bs[4 * q + 2], b3v = bs[4 * q + 3];
#pragma unroll
        for (int mt = 0; mt < 2; ++mt) {
            float* bl = g_seg + ((d * NSEG + seg_l[mt]) * BW + lr) * FOUT + 4 * q;
            float* bh = g_seg + ((d * NSEG + seg_h[mt]) * BW + lr) * FOUT + 4 * q;
            {
                const float v0 = fmaxf(acc[mt][0][0] + b0v, 0.f);
                const float v1 = fmaxf(acc[mt][0][1] + b1v, 0.f);
                const float v2 = fmaxf(acc[mt][1][0] + b2v, 0.f);
                const float v3 = fmaxf(acc[mt][1][1] + b3v, 0.f);
                asm volatile("red.global.add.v4.f32 [%0], {%1,%2,%3,%4};"
                             :: "l"(bl), "f"(v0), "f"(v1), "f"(v2), "f"(v3)
                             : "memory");
            }
            {
                const float v0 = fmaxf(acc[mt][0][2] + b0v, 0.f);
                const float v1 = fmaxf(acc[mt][0][3] + b1v, 0.f);
                const float v2 = fmaxf(acc[mt][1][2] + b2v, 0.f);
                const float v3 = fmaxf(acc[mt][1][3] + b3v, 0.f);
                asm volatile("red.global.add.v4.f32 [%0], {%1,%2,%3,%4};"
                             :: "l"(bh), "f"(v0), "f"(v1), "f"(v2), "f"(v3)
                             : "memory");
            }
        }
    }
}

// ---------------------------------------------------------------------------
// Kernel 2: post conv (3,1) + relu via fp16 HMMA.
// grid (NSEG/32, NDIM), block 256 (8 warps). CTA: 32 segments x 8 w = 256 rows,
// K=48 (3 seg-taps x 16 ch), N=16 filters. Same smem layout as pre_conv but
// 8 w-slots/seg (no w padding) and tap shift = a*64 words. Inputs load
// COALESCED from g_seg; output is plain STG.128 (no atomics).
// ---------------------------------------------------------------------------
#define XS2_WORDS (34 * 8 * 8)    // 2176
__global__ void __launch_bounds__(256)
post_conv_mma_kernel()
{
    __shared__ uint32_t xs2[XS2_WORDS];
    __shared__ uint32_t wb2[WB2_WORDS];
    __shared__ float    bs2[16];

    const int tid  = threadIdx.x;
    const int wid  = tid >> 5;
    const int lane = tid & 31;
    const int q    = lane & 3;
    const int lr   = lane >> 2;   // w position / B n index
    const int d    = blockIdx.y;
    const int s0   = blockIdx.x * 32;

    {
        const uint4* src = reinterpret_cast<const uint4*>(g_wb2 + d * WB2_WORDS);
        uint4* dst = reinterpret_cast<uint4*>(wb2);
        for (int i = tid; i < WB2_WORDS / 4; i += 256) dst[i] = src[i];
        if (tid < FOUT) bs2[tid] = g_bs2[d * FOUT + tid];
    }

    // Coalesced load + fp16 convert: 272 rows (34 seg x 8 w) x 4 quarters
    for (int i = tid; i < 34 * 8 * 4; i += 256) {
        const int row = i >> 2;
        const int tq  = i & 3;
        const int sh  = row >> 3;           // 0..33 (seg with halo)
        const int w   = row & 7;
        const int ss  = s0 - 1 + sh;
        float4 v = make_float4(0.f, 0.f, 0.f, 0.f);
        if ((unsigned)ss < NSEG)
            v = reinterpret_cast<const float4*>(
                g_seg + ((d * NSEG + ss) * BW + w) * FOUT)[tq];
        const int woff = (sh * 8 + w) * 8 + 4 * (tq & 1) + (tq >> 1);
        xs2[woff]     = pack_f16x2(v.x, v.y);
        xs2[woff + 2] = pack_f16x2(v.z, v.w);
    }
    __syncthreads();

    // m-tile mt: rows wid*32 + mt*16 + {lr, lr+8} -> (sl = wid*4 + mt*2 (+1), w = lr)
    // smem row for tap a = (sl + a)*8 + w  (halo offset built in: sh 0 = seg s0-1)
    int base_lo[2], base_hi[2];
#pragma unroll
    for (int mt = 0; mt < 2; ++mt) {
        const int sl = wid * 4 + mt * 2;
        base_lo[mt] = (sl * 8 + lr) * 8 + 2 * q;
        base_hi[mt] = base_lo[mt] + 64;     // sl+1 -> +8 rows
    }

    float acc[2][2][4];
#pragma unroll
    for (int mt = 0; mt < 2; ++mt)
#pragma unroll
        for (int nt = 0; nt < 2; ++nt)
#pragma unroll
            for (int i = 0; i < 4; ++i) acc[mt][nt][i] = 0.f;

#pragma unroll
    for (int a = 0; a < 3; ++a) {
        const int toff = a * 64;
        const uint2 bf0 = *reinterpret_cast<const uint2*>(
            wb2 + (a * 16 + lr) * 8 + 2 * q);
        const uint2 bf1 = *reinterpret_cast<const uint2*>(
            wb2 + (a * 16 + 8 + lr) * 8 + 2 * q);
#pragma unroll
        for (int mt = 0; mt < 2; ++mt) {
            const uint2 alo = *reinterpret_cast<const uint2*>(
                xs2 + base_lo[mt] + toff);
            const uint2 ahi = *reinterpret_cast<const uint2*>(
                xs2 + base_hi[mt] + toff);
            MMA_F16(acc[mt][0], alo.x, ahi.x, alo.y, ahi.y, bf0.x, bf0.y);
            MMA_F16(acc[mt][1], alo.x, ahi.x, alo.y, ahi.y, bf1.x, bf1.y);
        }
    }

    // Epilogue: bias + relu + STG.128; thread's cols are filters [4q, 4q+4)
    const float b0v = bs2[4 * q + 0], b1v = bs2[4 * q + 1];
    const float b2v = bs2[4 * q + 2], b3v = bs2[4 * q + 3];
#pragma unroll
    for (int mt = 0; mt < 2; ++mt) {
        const int sl = wid * 4 + mt * 2;
        float* dl = g_z + ((d * NSEG + s0 + sl) * BW + lr) * FOUT + 4 * q;
        float* dh = g_z + ((d * NSEG + s0 + sl + 1) * BW + lr) * FOUT + 4 * q;
        float4 o;
        o.x = fmaxf(acc[mt][0][0] + b0v, 0.f);
        o.y = fmaxf(acc[mt][0][1] + b1v, 0.f);
        o.z = fmaxf(acc[mt][1][0] + b2v, 0.f);
        o.w = fmaxf(acc[mt][1][1] + b3v, 0.f);
        *reinterpret_cast<float4*>(dl) = o;
        o.x = fmaxf(acc[mt][0][2] + b0v, 0.f);
        o.y = fmaxf(acc[mt][0][3] + b1v, 0.f);
        o.z = fmaxf(acc[mt][1][2] + b2v, 0.f);
        o.w = fmaxf(acc[mt][1][3] + b3v, 0.f);
        *reinterpret_cast<float4*>(dh) = o;
    }
}

// ---------------------------------------------------------------------------
// Kernel 3: Y[n,w,:] = sum_d g_z[d, index[d,n], w, :]
// ---------------------------------------------------------------------------
__global__ void __launch_bounds__(256)
gather_out_kernel(const int* __restrict__ index, float* __restrict__ out)
{
    const int gt = blockIdx.x * 256 + threadIdx.x;
    if (gt >= NPTS * BW * 2) return;
    const int n   = gt >> 5;
    const int rem = gt & 31;
    const int n2  = n + NPTS / 2;

    const int s0 = index[n],            t0 = index[n2];
    const int s1 = index[NPTS + n],     t1 = index[NPTS + n2];
    const int s2 = index[2 * NPTS + n], t2 = index[2 * NPTS + n2];

    const float4 a0 = reinterpret_cast<const float4*>(
        g_z + (size_t)s0 * (BW * FOUT))[rem];
    const float4 a1 = reinterpret_cast<const float4*>(
        g_z + (size_t)(NSEG + s1) * (BW * FOUT))[rem];
    const float4 a2 = reinterpret_cast<const float4*>(
        g_z + (size_t)(2 * NSEG + s2) * (BW * FOUT))[rem];
    const float4 c0 = reinterpret_cast<const float4*>(
        g_z + (size_t)t0 * (BW * FOUT))[rem];
    const float4 c1 = reinterpret_cast<const float4*>(
        g_z + (size_t)(NSEG + t1) * (BW * FOUT))[rem];
    const float4 c2 = reinterpret_cast<const float4*>(
        g_z + (size_t)(2 * NSEG + t2) * (BW * FOUT))[rem];

    float4 r;
    r.x = a0.x + a1.x + a2.x; r.y = a0.y + a1.y + a2.y;
    r.z = a0.z + a1.z + a2.z; r.w = a0.w + a1.w + a2.w;
    reinterpret_cast<float4*>(out)[n * 32 + rem] = r;

    float4 r2;
    r2.x = c0.x + c1.x + c2.x; r2.y = c0.y + c1.y + c2.y;
    r2.z = c0.z + c1.z + c2.z; r2.w = c0.w + c1.w + c2.w;
    reinterpret_cast<float4*>(out)[n2 * 32 + rem] = r2;
}

// ---------------------------------------------------------------------------
extern "C" void kernel_launch(void* const* d_in, const int* in_sizes, int n_in,
                              void* d_out, int out_size)
{
    const float* X      = (const float*)d_in[0];
    const int*   inv    = (const int*)  d_in[1];
    const int*   index  = (const int*)  d_in[2];
    const float* pre_w  = (const float*)d_in[3];
    const float* pre_b  = (const float*)d_in[4];
    const float* post_w = (const float*)d_in[5];
    const float* post_b = (const float*)d_in[6];
    float*       out    = (float*)      d_out;

    setup_kernel<<<2048, 256>>>(pre_w, pre_b, post_w, post_b);

    dim3 g1(NBX, NDIM);
    pre_conv_mma_kernel<<<g1, T1>>>(X, inv, index);

    dim3 g2(NSEG / 32, NDIM);
    post_conv_mma_kernel<<<g2, 256>>>();

    gather_out_kernel<<<(NPTS * BW * 2 + 255) / 256, 256>>>(index, out);
}

// round 17
// speedup vs baseline: 1.5332x; 1.2618x over previous
#include <cuda_runtime.h>
#include <cstdint>

// Problem constants
#define NPTS 100000
#define CIN  16
#define FOUT 16
#define BW   8
#define NDIM 3
#define NSEG 8192

// Pre-conv (fp16 mma.sync m16n8k16) tiling — R13/R16 proven configuration
#define PN    32                  // points per tile -> 256 output rows
#define T1    256                 // 8 warps; warp covers 32 rows (2 m16 tiles)
#define NTILE (NPTS / PN)         // 3125
#define TPC   5                   // tiles per CTA
#define NBX   (NTILE / TPC)       // 625
#define XS_WORDS (34 * 10 * 8)    // 2720
#define WB_WORDS (144 * 8)        // 1152  (pre weights)
#define WB2_WORDS (48 * 8)        // 384   (post weights)

__device__ __forceinline__ uint32_t pack_f16x2(float lo, float hi) {
    uint32_t r;
    asm("cvt.rn.f16x2.f32 %0, %1, %2;" : "=r"(r) : "f"(hi), "f"(lo));
    return r;
}

#define MMA_F16(acc, a0, a1, a2, a3, b0, b1)                                   \
    asm("mma.sync.aligned.m16n8k16.row.col.f32.f16.f16.f32 "                   \
        "{%0,%1,%2,%3},{%4,%5,%6,%7},{%8,%9},{%0,%1,%2,%3};"                   \
        : "+f"(acc[0]), "+f"(acc[1]), "+f"(acc[2]), "+f"(acc[3])               \
        : "r"(a0), "r"(a1), "r"(a2), "r"(a3), "r"(b0), "r"(b1))

// Device scratch (static allocation — no cudaMalloc allowed)
__device__ float    g_seg[NDIM * NSEG * BW * FOUT];   // segment sums
__device__ float    g_z  [NDIM * NSEG * BW * FOUT];   // post-conv output
__device__ uint32_t g_xh [NPTS * 8];                  // X as permuted fp16 pairs
__device__ uint32_t g_wb [NDIM * WB_WORDS];           // permuted fp16 pre weights
__device__ uint32_t g_wb2[NDIM * WB2_WORDS];          // permuted fp16 post weights
__device__ float    g_bs [NDIM * FOUT];               // pre bias
__device__ float    g_bs2[NDIM * FOUT];               // post bias

// ---------------------------------------------------------------------------
// Kernel 0: zero g_seg + convert X to permuted fp16 + build weights/biases.
// Permutation (word j of 8): w0=(c0,c1) w1=(c8,c9) w2=(c2,c3) w3=(c10,c11)
//                            w4=(c4,c5) w5=(c12,c13) w6=(c6,c7) w7=(c14,c15)
// ---------------------------------------------------------------------------
__global__ void setup_kernel(const float* __restrict__ X,
                             const float* __restrict__ pre_w,
                             const float* __restrict__ pre_b,
                             const float* __restrict__ post_w,
                             const float* __restrict__ post_b) {
    const int gt = blockIdx.x * blockDim.x + threadIdx.x;
    const int nthr = gridDim.x * blockDim.x;

    // Zero g_seg
    {
        const int total = NDIM * NSEG * BW * FOUT / 4;
        float4* p = reinterpret_cast<float4*>(g_seg);
        const float4 z = make_float4(0.f, 0.f, 0.f, 0.f);
        for (int i = gt; i < total; i += nthr) p[i] = z;
    }
    // Convert X rows -> g_xh (one point row per task)
    for (int n = gt; n < NPTS; n += nthr) {
        const float4* xp = reinterpret_cast<const float4*>(X) + n * 4;
        const float4 v0 = xp[0], v1 = xp[1], v2 = xp[2], v3 = xp[3];
        uint4 o0, o1;
        o0.x = pack_f16x2(v0.x, v0.y);   // (c0,c1)
        o0.y = pack_f16x2(v2.x, v2.y);   // (c8,c9)
        o0.z = pack_f16x2(v0.z, v0.w);   // (c2,c3)
        o0.w = pack_f16x2(v2.z, v2.w);   // (c10,c11)
        o1.x = pack_f16x2(v1.x, v1.y);   // (c4,c5)
        o1.y = pack_f16x2(v3.x, v3.y);   // (c12,c13)
        o1.z = pack_f16x2(v1.z, v1.w);   // (c6,c7)
        o1.w = pack_f16x2(v3.z, v3.w);   // (c14,c15)
        uint4* dst = reinterpret_cast<uint4*>(g_xh + n * 8);
        dst[0] = o0; dst[1] = o1;
    }
    // Pre-conv weights
    if (gt < NDIM * WB_WORDS) {
        const int d   = gt / WB_WORDS;
        const int i   = gt - d * WB_WORDS;
        const int tap = i >> 7;
        const int rem = i & 127;
        const int s   = rem >> 3;
        const int j   = rem & 7;
        const int nt  = s >> 3;
        const int n   = s & 7;
        const int fpm = 4 * (n >> 1) + 2 * nt + (n & 1);
        const int c   = (j & 1) ? (j + 7) : j;
        const int base = d * 2304 + tap * 256;
        g_wb[gt] = pack_f16x2(pre_w[base + c * 16 + fpm],
                              pre_w[base + (c + 1) * 16 + fpm]);
    }
    // Post-conv weights
    if (gt < NDIM * WB2_WORDS) {
        const int d   = gt / WB2_WORDS;
        const int i   = gt - d * WB2_WORDS;
        const int tap = i >> 7;
        const int rem = i & 127;
        const int s   = rem >> 3;
        const int j   = rem & 7;
        const int nt  = s >> 3;
        const int n   = s & 7;
        const int fpm = 4 * (n >> 1) + 2 * nt + (n & 1);
        const int c   = (j & 1) ? (j + 7) : j;
        const int base = d * 768 + tap * 256;
        g_wb2[gt] = pack_f16x2(post_w[base + c * 16 + fpm],
                               post_w[base + (c + 1) * 16 + fpm]);
    }
    if (gt < NDIM * FOUT) {
        g_bs [gt] = pre_b [gt];
        g_bs2[gt] = post_b[gt];
    }
}

// ---------------------------------------------------------------------------
// Kernel 1: gather g_xh[inv] (cp.async 16B x2/row) -> fp16 mma -> relu ->
// atomic seg-sum. grid (625,3), TPC=5 tiles/CTA.
// ---------------------------------------------------------------------------
__global__ void __launch_bounds__(T1)
pre_conv_mma_kernel(const int* __restrict__ inv, const int* __restrict__ index)
{
    __shared__ uint32_t xs[XS_WORDS];
    __shared__ uint32_t wb[WB_WORDS];
    __shared__ float    bs[16];

    const int tid  = threadIdx.x;
    const int wid  = tid >> 5;
    const int lane = tid & 31;
    const int q    = lane & 3;
    const int lr   = lane >> 2;
    const int d    = blockIdx.y;

    {
        const uint4* src = reinterpret_cast<const uint4*>(g_wb + d * WB_WORDS);
        uint4* dst = reinterpret_cast<uint4*>(wb);
        for (int i = tid; i < WB_WORDS / 4; i += T1) dst[i] = src[i];
        if (tid < FOUT) bs[tid] = g_bs[d * FOUT + tid];
        for (int i = tid; i < 34 * 16; i += T1) {
            const int pt = i >> 4, rem = i & 15;
            const int wslot = (rem < 8) ? 0 : 9;
            xs[(pt * 10 + wslot) * 8 + (rem & 7)] = 0u;
        }
    }

#pragma unroll 1
    for (int t = 0; t < TPC; ++t) {
        const int tile   = blockIdx.x + NBX * t;
        const int bstart = tile * PN;

        if (tile == 0) {
            for (int i = tid; i < 64; i += T1)
                xs[(0 * 10 + ((i >> 3) + 1)) * 8 + (i & 7)] = 0u;
        }
        if (tile == NTILE - 1) {
            for (int i = tid; i < 64; i += T1)
                xs[(33 * 10 + ((i >> 3) + 1)) * 8 + (i & 7)] = 0u;
        }
        __syncthreads();

        // cp.async gather: 272 rows x 2 halves = 544 tasks (16B each)
        for (int i = tid; i < 34 * 8 * 2; i += T1) {
            const int r  = i >> 1;
            const int h  = i & 1;
            const int pt = r >> 3;
            const int w  = r & 7;
            const int gp = bstart - 1 + pt;
            if ((unsigned)gp >= NPTS) continue;
            const int idx = inv[(d * NPTS + gp) * BW + w];
            const uint32_t saddr = (uint32_t)__cvta_generic_to_shared(
                xs + (pt * 10 + w + 1) * 8 + h * 4);
            const void* gaddr = g_xh + idx * 8 + h * 4;
            asm volatile("cp.async.ca.shared.global [%0], [%1], 16;"
                         :: "r"(saddr), "l"(gaddr) : "memory");
        }
        asm volatile("cp.async.commit_group;" ::: "memory");

        // Prefetch epilogue segment ids while cp.async drains
        int seg_l[2], seg_h[2];
#pragma unroll
        for (int mt = 0; mt < 2; ++mt) {
            const int ptl = wid * 4 + mt * 2;
            seg_l[mt] = index[d * NPTS + bstart + ptl];
            seg_h[mt] = index[d * NPTS + bstart + ptl + 1];
        }
        asm volatile("cp.async.wait_group 0;" ::: "memory");
        __syncthreads();

        int base_lo[2], base_hi[2];
#pragma unroll
        for (int mt = 0; mt < 2; ++mt) {
            const int ptl = wid * 4 + mt * 2;
            base_lo[mt] = (ptl * 10 + lr) * 8 + 2 * q;
            base_hi[mt] = base_lo[mt] + 80;
        }

        float acc[2][2][4];
#pragma unroll
        for (int mt = 0; mt < 2; ++mt)
#pragma unroll
            for (int nt = 0; nt < 2; ++nt)
#pragma unroll
                for (int i = 0; i < 4; ++i) acc[mt][nt][i] = 0.f;

#pragma unroll
        for (int a = 0; a < 3; ++a) {
#pragma unroll
            for (int b = 0; b < 3; ++b) {
                const int tap  = a * 3 + b;
                const int toff = (a * 10 + b) * 8;
                const uint2 bf0 = *reinterpret_cast<const uint2*>(
                    wb + (tap * 16 + lr) * 8 + 2 * q);
                const uint2 bf1 = *reinterpret_cast<const uint2*>(
                    wb + (tap * 16 + 8 + lr) * 8 + 2 * q);
#pragma unroll
                for (int mt = 0; mt < 2; ++mt) {
                    const uint2 alo = *reinterpret_cast<const uint2*>(
                        xs + base_lo[mt] + toff);
                    const uint2 ahi = *reinterpret_cast<const uint2*>(
                        xs + base_hi[mt] + toff);
                    MMA_F16(acc[mt][0], alo.x, ahi.x, alo.y, ahi.y, bf0.x, bf0.y);
                    MMA_F16(acc[mt][1], alo.x, ahi.x, alo.y, ahi.y, bf1.x, bf1.y);
                }
            }
        }
        __syncthreads();

        const float b0v = bs[4 * q + 0], b1v = bs[4 * q + 1];
        const float b2v = bs[4 * q + 2], b3v = bs[4 * q + 3];
#pragma unroll
        for (int mt = 0; mt < 2; ++mt) {
            float* bl = g_seg + ((d * NSEG + seg_l[mt]) * BW + lr) * FOUT + 4 * q;
            float* bh = g_seg + ((d * NSEG + seg_h[mt]) * BW + lr) * FOUT + 4 * q;
            {
                const float v0 = fmaxf(acc[mt][0][0] + b0v, 0.f);
                const float v1 = fmaxf(acc[mt][0][1] + b1v, 0.f);
                const float v2 = fmaxf(acc[mt][1][0] + b2v, 0.f);
                const float v3 = fmaxf(acc[mt][1][1] + b3v, 0.f);
                asm volatile("red.global.add.v4.f32 [%0], {%1,%2,%3,%4};"
                             :: "l"(bl), "f"(v0), "f"(v1), "f"(v2), "f"(v3)
                             : "memory");
            }
            {
                const float v0 = fmaxf(acc[mt][0][2] + b0v, 0.f);
                const float v1 = fmaxf(acc[mt][0][3] + b1v, 0.f);
                const float v2 = fmaxf(acc[mt][1][2] + b2v, 0.f);
                const float v3 = fmaxf(acc[mt][1][3] + b3v, 0.f);
                asm volatile("red.global.add.v4.f32 [%0], {%1,%2,%3,%4};"
                             :: "l"(bh), "f"(v0), "f"(v1), "f"(v2), "f"(v3)
                             : "memory");
            }
        }
    }
}

// ---------------------------------------------------------------------------
// Kernel 2: post conv (3,1) + relu via fp16 HMMA (R16 proven).
// ---------------------------------------------------------------------------
#define XS2_WORDS (34 * 8 * 8)    // 2176
__global__ void __launch_bounds__(256)
post_conv_mma_kernel()
{
    __shared__ uint32_t xs2[XS2_WORDS];
    __shared__ uint32_t wb2[WB2_WORDS];
    __shared__ float    bs2[16];

    const int tid  = threadIdx.x;
    const int wid  = tid >> 5;
    const int lane = tid & 31;
    const int q    = lane & 3;
    const int lr   = lane >> 2;
    const int d    = blockIdx.y;
    const int s0   = blockIdx.x * 32;

    {
        const uint4* src = reinterpret_cast<const uint4*>(g_wb2 + d * WB2_WORDS);
        uint4* dst = reinterpret_cast<uint4*>(wb2);
        for (int i = tid; i < WB2_WORDS / 4; i += 256) dst[i] = src[i];
        if (tid < FOUT) bs2[tid] = g_bs2[d * FOUT + tid];
    }

    for (int i = tid; i < 34 * 8 * 4; i += 256) {
        const int row = i >> 2;
        const int tq  = i & 3;
        const int sh  = row >> 3;
        const int w   = row & 7;
        const int ss  = s0 - 1 + sh;
        float4 v = make_float4(0.f, 0.f, 0.f, 0.f);
        if ((unsigned)ss < NSEG)
            v = reinterpret_cast<const float4*>(
                g_seg + ((d * NSEG + ss) * BW + w) * FOUT)[tq];
        const int woff = (sh * 8 + w) * 8 + 4 * (tq & 1) + (tq >> 1);
        xs2[woff]     = pack_f16x2(v.x, v.y);
        xs2[woff + 2] = pack_f16x2(v.z, v.w);
    }
    __syncthreads();

    int base_lo[2], base_hi[2];
#pragma unroll
    for (int mt = 0; mt < 2; ++mt) {
        const int sl = wid * 4 + mt * 2;
        base_lo[mt] = (sl * 8 + lr) * 8 + 2 * q;
        base_hi[mt] = base_lo[mt] + 64;
    }

    float acc[2][2][4];
#pragma unroll
    for (int mt = 0; mt < 2; ++mt)
#pragma unroll
        for (int nt = 0; nt < 2; ++nt)
#pragma unroll
            for (int i = 0; i < 4; ++i) acc[mt][nt][i] = 0.f;

#pragma unroll
    for (int a = 0; a < 3; ++a) {
        const int toff = a * 64;
        const uint2 bf0 = *reinterpret_cast<const uint2*>(
            wb2 + (a * 16 + lr) * 8 + 2 * q);
        const uint2 bf1 = *reinterpret_cast<const uint2*>(
            wb2 + (a * 16 + 8 + lr) * 8 + 2 * q);
#pragma unroll
        for (int mt = 0; mt < 2; ++mt) {
            const uint2 alo = *reinterpret_cast<const uint2*>(
                xs2 + base_lo[mt] + toff);
            const uint2 ahi = *reinterpret_cast<const uint2*>(
                xs2 + base_hi[mt] + toff);
            MMA_F16(acc[mt][0], alo.x, ahi.x, alo.y, ahi.y, bf0.x, bf0.y);
            MMA_F16(acc[mt][1], alo.x, ahi.x, alo.y, ahi.y, bf1.x, bf1.y);
        }
    }

    const float b0v = bs2[4 * q + 0], b1v = bs2[4 * q + 1];
    const float b2v = bs2[4 * q + 2], b3v = bs2[4 * q + 3];
#pragma unroll
    for (int mt = 0; mt < 2; ++mt) {
        const int sl = wid * 4 + mt * 2;
        float* dl = g_z + ((d * NSEG + s0 + sl) * BW + lr) * FOUT + 4 * q;
        float* dh = g_z + ((d * NSEG + s0 + sl + 1) * BW + lr) * FOUT + 4 * q;
        float4 o;
        o.x = fmaxf(acc[mt][0][0] + b0v, 0.f);
        o.y = fmaxf(acc[mt][0][1] + b1v, 0.f);
        o.z = fmaxf(acc[mt][1][0] + b2v, 0.f);
        o.w = fmaxf(acc[mt][1][1] + b3v, 0.f);
        *reinterpret_cast<float4*>(dl) = o;
        o.x = fmaxf(acc[mt][0][2] + b0v, 0.f);
        o.y = fmaxf(acc[mt][0][3] + b1v, 0.f);
        o.z = fmaxf(acc[mt][1][2] + b2v, 0.f);
        o.w = fmaxf(acc[mt][1][3] + b3v, 0.f);
        *reinterpret_cast<float4*>(dh) = o;
    }
}

// ---------------------------------------------------------------------------
// Kernel 3: Y[n,w,:] = sum_d g_z[d, index[d,n], w, :]
// Each thread: FOUR n's (n, +25k, +50k, +75k) -> 12 independent L2 loads.
// ---------------------------------------------------------------------------
#define NQ (NPTS / 4)   // 25000
__global__ void __launch_bounds__(256)
gather_out_kernel(const int* __restrict__ index, float* __restrict__ out)
{
    const int gt = blockIdx.x * 256 + threadIdx.x;   // 0 .. NQ*32-1
    if (gt >= NQ * 32) return;
    const int n   = gt >> 5;
    const int rem = gt & 31;

    float4 r[4];
#pragma unroll
    for (int kk = 0; kk < 4; ++kk) {
        const int nn = n + kk * NQ;
        const int s0 = index[nn];
        const int s1 = index[NPTS + nn];
        const int s2 = index[2 * NPTS + nn];
        const float4 a0 = reinterpret_cast<const float4*>(
            g_z + (size_t)s0 * (BW * FOUT))[rem];
        const float4 a1 = reinterpret_cast<const float4*>(
            g_z + (size_t)(NSEG + s1) * (BW * FOUT))[rem];
        const float4 a2 = reinterpret_cast<const float4*>(
            g_z + (size_t)(2 * NSEG + s2) * (BW * FOUT))[rem];
        r[kk].x = a0.x + a1.x + a2.x;
        r[kk].y = a0.y + a1.y + a2.y;
        r[kk].z = a0.z + a1.z + a2.z;
        r[kk].w = a0.w + a1.w + a2.w;
    }
#pragma unroll
    for (int kk = 0; kk < 4; ++kk)
        reinterpret_cast<float4*>(out)[(n + kk * NQ) * 32 + rem] = r[kk];
}

// ---------------------------------------------------------------------------
extern "C" void kernel_launch(void* const* d_in, const int* in_sizes, int n_in,
                              void* d_out, int out_size)
{
    const float* X      = (const float*)d_in[0];
    const int*   inv    = (const int*)  d_in[1];
    const int*   index  = (const int*)  d_in[2];
    const float* pre_w  = (const float*)d_in[3];
    const float* pre_b  = (const float*)d_in[4];
    const float* post_w = (const float*)d_in[5];
    const float* post_b = (const float*)d_in[6];
    float*       out    = (float*)      d_out;

    setup_kernel<<<2048, 256>>>(X, pre_w, pre_b, post_w, post_b);

    dim3 g1(NBX, NDIM);
    pre_conv_mma_kernel<<<g1, T1>>>(inv, index);

    dim3 g2(NSEG / 32, NDIM);
    post_conv_mma_kernel<<<g2, 256>>>();

    gather_out_kernel<<<(NQ * 32 + 255) / 256, 256>>>(index, out);
}